// round 4
// baseline (speedup 1.0000x reference)
#include <cuda_runtime.h>
#include <math_constants.h>

// Hausdorff loss: x,y (8, 4096, 3) fp32 -> scalar.
// Squared-distance trick: |q-t|^2 = |q|^2 + (|t|^2 - 2 q.t); min/max on squared
// values, one sqrt per batch at the end.
// FFMA2 (fma.rn.f32x2) processes TWO TARGETS per packed instruction.

#define NB 8        // batches
#define V 4096      // points per cloud
#define TS 2048     // targets per smem tile
#define TPAIRS (TS / 2)
#define THREADS 256
#define QPB 512     // queries per block (2 per thread)
#define CHUNKS (V / QPB)   // 8  -> grid 8 x 8 x 2 = 128 CTAs

__device__ unsigned g_max[NB];

// Two targets interleaved: (x0,x1)(y0,y1)(z0,z1)(w0,w1), w = |t|^2. 32 bytes.
struct __align__(16) TPair { float2 x, y, z, w; };

__device__ __forceinline__ unsigned long long pack2(float lo, float hi) {
    unsigned long long r;
    asm("mov.b64 %0, {%1, %2};" : "=l"(r) : "f"(lo), "f"(hi));
    return r;
}
__device__ __forceinline__ unsigned long long fma2(unsigned long long a,
                                                   unsigned long long b,
                                                   unsigned long long c) {
    unsigned long long d;
    asm("fma.rn.f32x2 %0, %1, %2, %3;" : "=l"(d) : "l"(a), "l"(b), "l"(c));
    return d;
}
__device__ __forceinline__ float2 unpack2(unsigned long long v) {
    float2 f;
    asm("mov.b64 {%0, %1}, %2;" : "=f"(f.x), "=f"(f.y) : "l"(v));
    return f;
}

__global__ void hd_init_kernel() {
    if (threadIdx.x < NB) g_max[threadIdx.x] = 0u;
}

__global__ void __launch_bounds__(THREADS, 1)
hd_main_kernel(const float* __restrict__ X, const float* __restrict__ Y) {
    __shared__ TPair sT[TPAIRS];
    __shared__ float wmax[THREADS / 32];

    const int b   = blockIdx.y;
    const int dir = blockIdx.z;
    const float* __restrict__ Qp = (dir == 0 ? X : Y) + (size_t)b * V * 3;
    const float* __restrict__ Tp = (dir == 0 ? Y : X) + (size_t)b * V * 3;

    const int tid = threadIdx.x;
    const int q0 = blockIdx.x * QPB + tid;
    const int q1 = q0 + THREADS;

    // Query points; coefficients duplicated into f32x2 register pairs (once).
    const float q0x = Qp[q0 * 3 + 0], q0y = Qp[q0 * 3 + 1], q0z = Qp[q0 * 3 + 2];
    const float q1x = Qp[q1 * 3 + 0], q1y = Qp[q1 * 3 + 1], q1z = Qp[q1 * 3 + 2];
    const unsigned long long A0x = pack2(-2.0f * q0x, -2.0f * q0x);
    const unsigned long long A0y = pack2(-2.0f * q0y, -2.0f * q0y);
    const unsigned long long A0z = pack2(-2.0f * q0z, -2.0f * q0z);
    const unsigned long long A1x = pack2(-2.0f * q1x, -2.0f * q1x);
    const unsigned long long A1y = pack2(-2.0f * q1y, -2.0f * q1y);
    const unsigned long long A1z = pack2(-2.0f * q1z, -2.0f * q1z);
    const float q2_0 = q0x * q0x + q0y * q0y + q0z * q0z;
    const float q2_1 = q1x * q1x + q1y * q1y + q1z * q1z;

    // Four scalar min accumulators (query {0,1} x packed-half {lo,hi}).
    float m0a = CUDART_INF_F, m0b = CUDART_INF_F;
    float m1a = CUDART_INF_F, m1b = CUDART_INF_F;

    #pragma unroll
    for (int t = 0; t < V / TS; t++) {
        __syncthreads();
        // Cooperative load: target i -> pair i/2, half i&1.
        for (int i = tid; i < TS; i += THREADS) {
            const int g = t * TS + i;
            const float tx = Tp[g * 3 + 0];
            const float ty = Tp[g * 3 + 1];
            const float tz = Tp[g * 3 + 2];
            const float tw = tx * tx + ty * ty + tz * tz;
            float* dst = (float*)&sT[i >> 1];
            const int h = i & 1;
            dst[0 + h] = tx;
            dst[2 + h] = ty;
            dst[4 + h] = tz;
            dst[6 + h] = tw;
        }
        __syncthreads();

        #pragma unroll 8
        for (int j = 0; j < TPAIRS; j++) {
            // Two broadcast LDS.128: (x2,y2) and (z2,w2) packed pairs.
            const ulonglong2* sp = reinterpret_cast<const ulonglong2*>(&sT[j]);
            const ulonglong2 xy = sp[0];
            const ulonglong2 zw = sp[1];
            // v = |t|^2 - 2 q.t for two targets at once.
            const unsigned long long v0 =
                fma2(A0x, xy.x, fma2(A0y, xy.y, fma2(A0z, zw.x, zw.y)));
            const unsigned long long v1 =
                fma2(A1x, xy.x, fma2(A1y, xy.y, fma2(A1z, zw.x, zw.y)));
            const float2 f0 = unpack2(v0);   // register naming only
            const float2 f1 = unpack2(v1);
            m0a = fminf(m0a, f0.x);  m0b = fminf(m0b, f0.y);
            m1a = fminf(m1a, f1.x);  m1b = fminf(m1b, f1.y);
        }
    }

    const float s0 = fmaxf(q2_0 + fminf(m0a, m0b), 0.0f);
    const float s1 = fmaxf(q2_1 + fminf(m1a, m1b), 0.0f);
    float m = fmaxf(s0, s1);

    #pragma unroll
    for (int off = 16; off > 0; off >>= 1)
        m = fmaxf(m, __shfl_xor_sync(0xffffffffu, m, off));
    if ((tid & 31) == 0) wmax[tid >> 5] = m;
    __syncthreads();

    if (tid == 0) {
        float mm = wmax[0];
        #pragma unroll
        for (int w = 1; w < THREADS / 32; w++) mm = fmaxf(mm, wmax[w]);
        // Nonnegative floats: uint ordering == float ordering.
        atomicMax(&g_max[b], __float_as_uint(mm));
    }
}

__global__ void hd_final_kernel(float* __restrict__ out) {
    if (threadIdx.x == 0) {
        float s = 0.0f;
        #pragma unroll
        for (int i = 0; i < NB; i++) s += sqrtf(__uint_as_float(g_max[i]));
        out[0] = s * (1.0f / (float)NB);   // LOSS_WEIGHT = 1.0
    }
}

extern "C" void kernel_launch(void* const* d_in, const int* in_sizes, int n_in,
                              void* d_out, int out_size) {
    const float* x = (const float*)d_in[0];
    const float* y = (const float*)d_in[1];
    float* out = (float*)d_out;

    hd_init_kernel<<<1, 32>>>();
    dim3 grid(CHUNKS, NB, 2);
    hd_main_kernel<<<grid, THREADS>>>(x, y);
    hd_final_kernel<<<1, 32>>>(out);
}